// round 3
// baseline (speedup 1.0000x reference)
#include <cuda_runtime.h>
#include <math.h>

#define SEQ   1024
#define BATCH 128
#define EMB   512
#define HID   512
#define ZDIM  2048               // 4*HID
#define NBH   (BATCH * HID)      // 65536
#define NBLK  64                 // persistent grid: 32 j-tiles x 2 row-tiles

// Scratch (allocation-free rule: __device__ globals)
__device__ float    g_xz[(size_t)SEQ * BATCH * ZDIM];   // 1 GiB: x@Wx + b
__device__ float    g_c[NBH];                           // cell state
__device__ unsigned g_count;                            // barrier arrivals
__device__ unsigned g_phase;                            // barrier phase

// ---------------------------------------------------------------------------
// helpers
// ---------------------------------------------------------------------------
__device__ __forceinline__ unsigned tf32cvt(float x) {
    unsigned u;
    asm("cvt.rna.tf32.f32 %0, %1;" : "=r"(u) : "f"(x));
    return u;
}

__device__ __forceinline__ void mma_tf32(float* c, const unsigned* a, const unsigned* b) {
    asm volatile(
        "mma.sync.aligned.m16n8k8.row.col.f32.tf32.tf32.f32 "
        "{%0,%1,%2,%3}, {%4,%5,%6,%7}, {%8,%9}, {%0,%1,%2,%3};\n"
        : "+f"(c[0]), "+f"(c[1]), "+f"(c[2]), "+f"(c[3])
        : "r"(a[0]), "r"(a[1]), "r"(a[2]), "r"(a[3]), "r"(b[0]), "r"(b[1]));
}

__device__ __forceinline__ float sigmoid_(float x) {
    return 1.0f / (1.0f + __expf(-x));
}
__device__ __forceinline__ float tanh_(float x) {
    float ax = fabsf(x);
    float e  = __expf(-2.0f * ax);
    float r  = (1.0f - e) / (1.0f + e);
    return x >= 0.0f ? r : -r;
}

// ---------------------------------------------------------------------------
// reset barrier state (graph node 1; makes replays deterministic)
// ---------------------------------------------------------------------------
__global__ void reset_k() {
    g_count = 0;
    g_phase = 0;
}

// ---------------------------------------------------------------------------
// Precompute: g_xz[m, n] = sum_k X[m,k] * W[k,n] + b[n]
// M = SEQ*BATCH = 131072, N = ZDIM = 2048, K = EMB = 512
// Block tile 128x128x16, 256 threads (8 warps, warp tile 64x32), tf32 mma.
// ---------------------------------------------------------------------------
__global__ __launch_bounds__(256) void gemm_xz_k(const float* __restrict__ X,
                                                 const float* __restrict__ W,
                                                 const float* __restrict__ bias) {
    __shared__ unsigned As[128][17];
    __shared__ unsigned Bs[16][136];

    const int bn = blockIdx.x;
    const int bm = blockIdx.y;
    const int tid  = threadIdx.x;
    const int lane = tid & 31;
    const int w    = tid >> 5;
    const int wm = (w & 1) * 64;
    const int wn = (w >> 1) * 32;
    const int gid = lane >> 2;
    const int tig = lane & 3;

    float acc[4][4][4];
    #pragma unroll
    for (int mt = 0; mt < 4; mt++)
        #pragma unroll
        for (int nt = 0; nt < 4; nt++)
            #pragma unroll
            for (int r = 0; r < 4; r++) acc[mt][nt][r] = 0.0f;

    const float* Ag = X + (size_t)bm * 128 * EMB;
    const float* Bg = W + (size_t)bn * 128;

    for (int k0 = 0; k0 < EMB; k0 += 16) {
        #pragma unroll
        for (int i = 0; i < 2; i++) {
            int idx = tid + i * 256;
            int r = idx >> 2, c4 = idx & 3;
            float4 v = *(const float4*)(Ag + (size_t)r * EMB + k0 + c4 * 4);
            As[r][c4 * 4 + 0] = tf32cvt(v.x);
            As[r][c4 * 4 + 1] = tf32cvt(v.y);
            As[r][c4 * 4 + 2] = tf32cvt(v.z);
            As[r][c4 * 4 + 3] = tf32cvt(v.w);
        }
        #pragma unroll
        for (int i = 0; i < 2; i++) {
            int idx = tid + i * 256;
            int r = idx >> 5, c4 = idx & 31;
            float4 v = *(const float4*)(Bg + (size_t)(k0 + r) * ZDIM + c4 * 4);
            Bs[r][c4 * 4 + 0] = tf32cvt(v.x);
            Bs[r][c4 * 4 + 1] = tf32cvt(v.y);
            Bs[r][c4 * 4 + 2] = tf32cvt(v.z);
            Bs[r][c4 * 4 + 3] = tf32cvt(v.w);
        }
        __syncthreads();

        #pragma unroll
        for (int kk = 0; kk < 16; kk += 8) {
            unsigned a[4][4], b[4][2];
            #pragma unroll
            for (int mt = 0; mt < 4; mt++) {
                int mr = wm + mt * 16;
                a[mt][0] = As[mr + gid][kk + tig];
                a[mt][1] = As[mr + gid + 8][kk + tig];
                a[mt][2] = As[mr + gid][kk + tig + 4];
                a[mt][3] = As[mr + gid + 8][kk + tig + 4];
            }
            #pragma unroll
            for (int nt = 0; nt < 4; nt++) {
                int nc = wn + nt * 8;
                b[nt][0] = Bs[kk + tig][nc + gid];
                b[nt][1] = Bs[kk + tig + 4][nc + gid];
            }
            #pragma unroll
            for (int mt = 0; mt < 4; mt++)
                #pragma unroll
                for (int nt = 0; nt < 4; nt++)
                    mma_tf32(acc[mt][nt], a[mt], b[nt]);
        }
        __syncthreads();
    }

    #pragma unroll
    for (int mt = 0; mt < 4; mt++) {
        #pragma unroll
        for (int nt = 0; nt < 4; nt++) {
            int grow = bm * 128 + wm + mt * 16 + gid;
            int gcol = bn * 128 + wn + nt * 8 + 2 * tig;
            float b0 = bias[gcol], b1 = bias[gcol + 1];
            float* p0 = g_xz + (size_t)grow * ZDIM + gcol;
            p0[0] = acc[mt][nt][0] + b0;
            p0[1] = acc[mt][nt][1] + b1;
            float* p1 = g_xz + (size_t)(grow + 8) * ZDIM + gcol;
            p1[0] = acc[mt][nt][2] + b0;
            p1[1] = acc[mt][nt][3] + b1;
        }
    }
}

// ---------------------------------------------------------------------------
// grid-wide barrier for the persistent kernel (64 co-resident CTAs)
// ---------------------------------------------------------------------------
__device__ __forceinline__ void grid_sync(unsigned target) {
    __syncthreads();
    if (threadIdx.x == 0) {
        __threadfence();
        unsigned arrived = atomicAdd(&g_count, 1u);
        if (arrived == NBLK - 1) {
            atomicExch(&g_count, 0u);
            __threadfence();
            atomicAdd(&g_phase, 1u);   // release
        } else {
            while (atomicAdd(&g_phase, 0u) < target) { __nanosleep(32); }
        }
        __threadfence();
    }
    __syncthreads();
}

// ---------------------------------------------------------------------------
// Persistent LSTM: all 1024 timesteps in one launch.
// Grid: (32 j-tiles, 2 row-tiles) = 64 CTAs, 128 threads each.
// CTA tile per step: 64 batch rows x 16 hidden cols (= 64 z-cols, all 4 gates).
// Wh slice (512 x 64 tf32, gate-gathered) is cached in smem for ALL steps.
// Warp layout: 4 warps, 32x32 tiles (2x2 over the 64x64 output).
// Dynamic smem: Bs[512][72] | As[64][132] | Zs[64][65]  = 197888 B
// ---------------------------------------------------------------------------
#define SMEM_WORDS_B (512 * 72)
#define SMEM_WORDS_A (64 * 132)
#define SMEM_BYTES   ((SMEM_WORDS_B + SMEM_WORDS_A + 64 * 65) * 4)

__global__ __launch_bounds__(128, 1) void lstm_persist_k(float* __restrict__ out,
                                                         const float* __restrict__ W) {
    extern __shared__ unsigned smem_u[];
    unsigned (*Bs)[72]  = (unsigned(*)[72])smem_u;
    unsigned (*As)[132] = (unsigned(*)[132])(smem_u + SMEM_WORDS_B);
    float    (*Zs)[65]  = (float(*)[65])(smem_u + SMEM_WORDS_B + SMEM_WORDS_A);

    const int bj   = blockIdx.x;          // 0..31
    const int bm   = blockIdx.y;          // 0..1
    const int j0   = bj * 16;
    const int row0 = bm * 64;
    const int tid  = threadIdx.x;
    const int lane = tid & 31;
    const int w    = tid >> 5;            // 0..3
    const int wm   = (w & 1) * 32;        // warp m offset
    const int wn   = (w >> 1) * 32;       // warp n offset
    const int gid  = lane >> 2;
    const int tig  = lane & 3;

    const float* Wh = W + (size_t)EMB * ZDIM;

    // ---- one-time: cache Wh slice (gate-gathered, tf32) in smem ----
    #pragma unroll 4
    for (int i = 0; i < 64; i++) {
        int idx  = tid + i * 128;
        int br   = idx >> 4;                 // k row 0..511
        int n    = (idx & 15) * 4;           // 0..60, within one gate segment
        int gate = n >> 4, jj = n & 15;
        float4 v = *(const float4*)(Wh + (size_t)br * ZDIM + gate * 512 + j0 + jj);
        *(uint4*)&Bs[br][n] = make_uint4(tf32cvt(v.x), tf32cvt(v.y),
                                         tf32cvt(v.z), tf32cvt(v.w));
    }
    // ---- one-time: zero own cell-state tile ----
    #pragma unroll
    for (int it = 0; it < 8; it++) {
        int item = tid + it * 128;
        int jj = item & 15, b = item >> 4;
        g_c[(size_t)(row0 + b) * HID + j0 + jj] = 0.0f;
    }
    __syncthreads();

    for (int t = 0; t < SEQ; t++) {
        float acc[2][4][4];
        #pragma unroll
        for (int mt = 0; mt < 2; mt++)
            #pragma unroll
            for (int nt = 0; nt < 4; nt++)
                #pragma unroll
                for (int r = 0; r < 4; r++) acc[mt][nt][r] = 0.0f;

        if (t > 0) {
            const float* hprev = out + (size_t)(t - 1) * NBH;
            #pragma unroll 1
            for (int kc = 0; kc < 4; kc++) {
                const int k0 = kc * 128;
                // load A chunk: 64 rows x 128 k (tf32), 16 float4/thread
                #pragma unroll
                for (int i = 0; i < 16; i++) {
                    int idx = tid + i * 128;
                    int r = idx >> 5, c4 = idx & 31;
                    float4 v = *(const float4*)(hprev + (size_t)(row0 + r) * HID + k0 + c4 * 4);
                    *(uint4*)&As[r][c4 * 4] = make_uint4(tf32cvt(v.x), tf32cvt(v.y),
                                                         tf32cvt(v.z), tf32cvt(v.w));
                }
                __syncthreads();

                #pragma unroll
                for (int kk = 0; kk < 128; kk += 8) {
                    unsigned a[2][4], b[4][2];
                    #pragma unroll
                    for (int mt = 0; mt < 2; mt++) {
                        int mr = wm + mt * 16;
                        a[mt][0] = As[mr + gid][kk + tig];
                        a[mt][1] = As[mr + gid + 8][kk + tig];
                        a[mt][2] = As[mr + gid][kk + tig + 4];
                        a[mt][3] = As[mr + gid + 8][kk + tig + 4];
                    }
                    #pragma unroll
                    for (int nt = 0; nt < 4; nt++) {
                        int nc = wn + nt * 8;
                        b[nt][0] = Bs[k0 + kk + tig][nc + gid];
                        b[nt][1] = Bs[k0 + kk + tig + 4][nc + gid];
                    }
                    #pragma unroll
                    for (int mt = 0; mt < 2; mt++)
                        #pragma unroll
                        for (int nt = 0; nt < 4; nt++)
                            mma_tf32(acc[mt][nt], a[mt], b[nt]);
                }
                __syncthreads();
            }
        }

        // ---- scatter recurrent z to smem for gate exchange ----
        #pragma unroll
        for (int mt = 0; mt < 2; mt++) {
            #pragma unroll
            for (int nt = 0; nt < 4; nt++) {
                int rr  = wm + mt * 16 + gid;
                int col = wn + nt * 8 + 2 * tig;
                Zs[rr][col]         = acc[mt][nt][0];
                Zs[rr][col + 1]     = acc[mt][nt][1];
                Zs[rr + 8][col]     = acc[mt][nt][2];
                Zs[rr + 8][col + 1] = acc[mt][nt][3];
            }
        }
        __syncthreads();

        // ---- gates + state update: 64x16 items, 8 per thread ----
        const float* xzt  = g_xz + (size_t)t * BATCH * ZDIM;
        float*       hout = out + (size_t)t * NBH;
        #pragma unroll
        for (int it = 0; it < 8; it++) {
            int item = tid + it * 128;
            int jj = item & 15;
            int b  = item >> 4;
            const float* xr = xzt + (size_t)(row0 + b) * ZDIM + j0 + jj;
            float zi = Zs[b][jj]      + xr[0];
            float zf = Zs[b][16 + jj] + xr[512];
            float zg = Zs[b][32 + jj] + xr[1024];
            float zo = Zs[b][48 + jj] + xr[1536];

            float ig = sigmoid_(zi);
            float fg = sigmoid_(zf);
            float gg = tanh_(zg);
            float og = sigmoid_(zo);

            size_t ci = (size_t)(row0 + b) * HID + j0 + jj;
            float cn  = fg * g_c[ci] + ig * gg;
            g_c[ci]   = cn;
            hout[ci]  = og * tanh_(cn);
        }

        // all h_t visible chip-wide before anyone loads it at t+1
        grid_sync((unsigned)(t + 1));
    }

    // ---- epilogue: append hT and cT (each CTA copies its own tile) ----
    float* hT = out + (size_t)SEQ * NBH;
    float* cT = hT + NBH;
    const float* hlast = out + (size_t)(SEQ - 1) * NBH;
    #pragma unroll
    for (int it = 0; it < 8; it++) {
        int item = tid + it * 128;
        int jj = item & 15, b = item >> 4;
        size_t ci = (size_t)(row0 + b) * HID + j0 + jj;
        hT[ci] = hlast[ci];
        cT[ci] = g_c[ci];
    }
}

// ---------------------------------------------------------------------------
extern "C" void kernel_launch(void* const* d_in, const int* in_sizes, int n_in,
                              void* d_out, int out_size) {
    const float* x    = (const float*)d_in[0];
    const float* W    = (const float*)d_in[1];
    const float* bias = (const float*)d_in[2];
    float* out = (float*)d_out;

    cudaFuncSetAttribute(lstm_persist_k,
                         cudaFuncAttributeMaxDynamicSharedMemorySize, SMEM_BYTES);

    reset_k<<<1, 1>>>();
    gemm_xz_k<<<dim3(ZDIM / 128, (SEQ * BATCH) / 128), 256>>>(x, W, bias);
    lstm_persist_k<<<dim3(32, 2), 128, SMEM_BYTES>>>(out, W);
}

// round 5
// speedup vs baseline: 2.2572x; 2.2572x over previous
#include <cuda_runtime.h>
#include <math.h>
#include <cstdint>

#define SEQ   1024
#define BATCH 128
#define EMB   512
#define HID   512
#define ZDIM  2048               // 4*HID
#define NBH   (BATCH * HID)      // 65536
#define NREC  64                 // recurrent CTAs (32 j-tiles x 2 row-tiles)
#define NPROD 84                 // xz-producer CTAs
#define NTILE (SEQ * 16)         // xz tiles: 1024 timesteps x 16 n-tiles

// Scratch (allocation-free rule: __device__ globals)
__device__ float    g_xz[(size_t)SEQ * BATCH * ZDIM];   // 1 GiB: x@Wx + b
__device__ unsigned g_count;                            // barrier arrivals
__device__ unsigned g_phase;                            // barrier phase
__device__ unsigned g_ready[SEQ];                       // xz tiles done per t

// ---------------------------------------------------------------------------
// helpers
// ---------------------------------------------------------------------------
__device__ __forceinline__ unsigned tf32cvt(float x) {
    unsigned u;
    asm("cvt.rna.tf32.f32 %0, %1;" : "=r"(u) : "f"(x));
    return u;
}

__device__ __forceinline__ void mma_tf32(float* c, const unsigned* a, const unsigned* b) {
    asm volatile(
        "mma.sync.aligned.m16n8k8.row.col.f32.tf32.tf32.f32 "
        "{%0,%1,%2,%3}, {%4,%5,%6,%7}, {%8,%9}, {%0,%1,%2,%3};\n"
        : "+f"(c[0]), "+f"(c[1]), "+f"(c[2]), "+f"(c[3])
        : "r"(a[0]), "r"(a[1]), "r"(a[2]), "r"(a[3]), "r"(b[0]), "r"(b[1]));
}

__device__ __forceinline__ float tanh_ap(float x) {
    float y;
    asm("tanh.approx.f32 %0, %1;" : "=f"(y) : "f"(x));
    return y;
}
__device__ __forceinline__ float sigm_ap(float x) {
    return fmaf(tanh_ap(0.5f * x), 0.5f, 0.5f);
}

// ---------------------------------------------------------------------------
// reset (graph node 1): barrier + ready flags -> deterministic replays
// ---------------------------------------------------------------------------
__global__ void reset_k() {
    int i = threadIdx.x;
    if (i < SEQ) g_ready[i] = 0;
    if (i == 0) { g_count = 0; g_phase = 0; }
}

// ---------------------------------------------------------------------------
// Dynamic smem layout (word offsets), recurrent-CTA view:
//   Bs  [512][72]  : Wh slice, gate-gathered (cached all steps)   147456 B
//   As0 [64][132]  : h chunk, K-group 0                            33792 B
//   As1 [64][132]  : h chunk, K-group 1                            33792 B
//   Zs  [64][65]   : z exchange                                    16640 B
// Producer-CTA view (overlay at word 0): Asp[128][17] | Bsp[16][136]
// ---------------------------------------------------------------------------
#define BS_STR  72
#define AS_STR  132
#define SM_AS0  (512 * BS_STR)
#define SM_AS1  (SM_AS0 + 64 * AS_STR)
#define SM_ZS   (SM_AS1 + 64 * AS_STR)
#define SMEM_WORDS (SM_ZS + 64 * 65)
#define SMEM_BYTES (SMEM_WORDS * 4)          // 231680 <= 232448 max

// ---------------------------------------------------------------------------
// Producer role: compute g_xz tiles (128 rows = one timestep, 128 cols) in
// t-order, publish g_ready[t]. Body = R3's verified gemm_xz tile.
// ---------------------------------------------------------------------------
__device__ void xz_producer(const float* __restrict__ X,
                            const float* __restrict__ W,
                            const float* __restrict__ bias,
                            unsigned* smw, int pid) {
    unsigned (*As)[17]  = (unsigned(*)[17])smw;
    unsigned (*Bs)[136] = (unsigned(*)[136])(smw + 128 * 17);

    const int tid  = threadIdx.x;
    const int lane = tid & 31;
    const int w    = tid >> 5;
    const int wm = (w & 1) * 64;
    const int wn = (w >> 1) * 32;
    const int gid = lane >> 2;
    const int tig = lane & 3;

    for (int idx = pid; idx < NTILE; idx += NPROD) {
        const int t  = idx >> 4;
        const int bn = idx & 15;

        float acc[4][4][4];
        #pragma unroll
        for (int mt = 0; mt < 4; mt++)
            #pragma unroll
            for (int nt = 0; nt < 4; nt++)
                #pragma unroll
                for (int r = 0; r < 4; r++) acc[mt][nt][r] = 0.0f;

        const float* Ag = X + (size_t)t * 128 * EMB;
        const float* Bg = W + (size_t)bn * 128;

        for (int k0 = 0; k0 < EMB; k0 += 16) {
            #pragma unroll
            for (int i = 0; i < 2; i++) {
                int id2 = tid + i * 256;
                int r = id2 >> 2, c4 = id2 & 3;
                float4 v = *(const float4*)(Ag + (size_t)r * EMB + k0 + c4 * 4);
                As[r][c4 * 4 + 0] = tf32cvt(v.x);
                As[r][c4 * 4 + 1] = tf32cvt(v.y);
                As[r][c4 * 4 + 2] = tf32cvt(v.z);
                As[r][c4 * 4 + 3] = tf32cvt(v.w);
            }
            #pragma unroll
            for (int i = 0; i < 2; i++) {
                int id2 = tid + i * 256;
                int r = id2 >> 5, c4 = id2 & 31;
                float4 v = *(const float4*)(Bg + (size_t)(k0 + r) * ZDIM + c4 * 4);
                Bs[r][c4 * 4 + 0] = tf32cvt(v.x);
                Bs[r][c4 * 4 + 1] = tf32cvt(v.y);
                Bs[r][c4 * 4 + 2] = tf32cvt(v.z);
                Bs[r][c4 * 4 + 3] = tf32cvt(v.w);
            }
            __syncthreads();

            #pragma unroll
            for (int kk = 0; kk < 16; kk += 8) {
                unsigned a[4][4], b[4][2];
                #pragma unroll
                for (int mt = 0; mt < 4; mt++) {
                    int mr = wm + mt * 16;
                    a[mt][0] = As[mr + gid][kk + tig];
                    a[mt][1] = As[mr + gid + 8][kk + tig];
                    a[mt][2] = As[mr + gid][kk + tig + 4];
                    a[mt][3] = As[mr + gid + 8][kk + tig + 4];
                }
                #pragma unroll
                for (int nt = 0; nt < 4; nt++) {
                    int nc = wn + nt * 8;
                    b[nt][0] = Bs[kk + tig][nc + gid];
                    b[nt][1] = Bs[kk + tig + 4][nc + gid];
                }
                #pragma unroll
                for (int mt = 0; mt < 4; mt++)
                    #pragma unroll
                    for (int nt = 0; nt < 4; nt++)
                        mma_tf32(acc[mt][nt], a[mt], b[nt]);
            }
            __syncthreads();
        }

        #pragma unroll
        for (int mt = 0; mt < 4; mt++) {
            #pragma unroll
            for (int nt = 0; nt < 4; nt++) {
                int grow = t * 128 + wm + mt * 16 + gid;
                int gcol = bn * 128 + wn + nt * 8 + 2 * tig;
                float b0 = bias[gcol], b1 = bias[gcol + 1];
                float* p0 = g_xz + (size_t)grow * ZDIM + gcol;
                p0[0] = acc[mt][nt][0] + b0;
                p0[1] = acc[mt][nt][1] + b1;
                float* p1 = g_xz + (size_t)(grow + 8) * ZDIM + gcol;
                p1[0] = acc[mt][nt][2] + b0;
                p1[1] = acc[mt][nt][3] + b1;
            }
        }

        __threadfence();          // every thread's STGs visible before flag
        __syncthreads();
        if (tid == 0) atomicAdd(&g_ready[t], 1u);
        __syncthreads();
    }
}

// ---------------------------------------------------------------------------
// grid barrier among the NREC recurrent CTAs (all co-resident, 1 wave)
// ---------------------------------------------------------------------------
__device__ __forceinline__ void grid_sync(unsigned target) {
    __threadfence();             // every thread's h-writes visible chip-wide
    __syncthreads();
    if (threadIdx.x == 0) {
        unsigned arrived = atomicAdd(&g_count, 1u);
        if (arrived == NREC - 1) {
            atomicExch(&g_count, 0u);
            atomicAdd(&g_phase, 1u);
        } else {
            while (atomicAdd(&g_phase, 0u) < target) { __nanosleep(32); }
        }
    }
    __syncthreads();
}

// ---------------------------------------------------------------------------
// Persistent kernel: 148 CTAs x 256 threads, one wave.
//   blockIdx.x <  64 : recurrent role (CTA tile M=64 rows x 16 hid cols)
//   blockIdx.x >= 64 : xz-producer role
//
// Recurrent GEMM per step: z[64 x 64] = h_prev[64 x 512] @ WhSlice[512 x 64].
// 8 warps: warp-quad q=w&3 tiles the 64x64 output with 32x32 warp tiles;
// group g=w>>2 K-splits: g0 sums k-chunks {[0,128),[256,384)},
// g1 sums {[128,256),[384,512)}; partials reduced through Zs.
// Cell state: 4 fp32 regs/thread. xz prefetched to regs at step start.
// ---------------------------------------------------------------------------
__global__ __launch_bounds__(256, 1) void lstm_persist_k(float* __restrict__ out,
                                                         const float* __restrict__ X,
                                                         const float* __restrict__ W,
                                                         const float* __restrict__ bias) {
    extern __shared__ unsigned smw[];
    const int tid = threadIdx.x;

    if (blockIdx.x >= NREC) {
        xz_producer(X, W, bias, smw, blockIdx.x - NREC);
        return;
    }

    unsigned (*Bs)[BS_STR]  = (unsigned(*)[BS_STR])smw;
    unsigned (*As0)[AS_STR] = (unsigned(*)[AS_STR])(smw + SM_AS0);
    unsigned (*As1)[AS_STR] = (unsigned(*)[AS_STR])(smw + SM_AS1);
    float    (*Zs)[65]      = (float(*)[65])(smw + SM_ZS);

    const int cb   = blockIdx.x;
    const int j0   = (cb & 31) * 16;      // hidden-col tile
    const int row0 = (cb >> 5) * 64;      // batch-row tile
    const int lane = tid & 31;
    const int w    = tid >> 5;
    const int grp  = w >> 2;              // K-split group
    const int wq   = w & 3;               // warp within group
    const int wm   = (wq & 1) * 32;
    const int wn   = (wq >> 1) * 32;
    const int gid  = lane >> 2;
    const int tig  = lane & 3;

    // ---- one-time: cache Wh slice (gate-gathered, tf32) in smem ----
    // Bs[k][n], n = gate*16 + jj  ->  Wh[k][gate*512 + j0 + jj]
    const float* Wh = W + (size_t)EMB * ZDIM;
    #pragma unroll 4
    for (int i = 0; i < 32; i++) {
        int idx  = tid + i * 256;            // 8192 float4s
        int k    = idx >> 4;
        int rem  = idx & 15;
        int gate = rem >> 2, jjq = rem & 3;
        float4 v = *(const float4*)(Wh + (size_t)k * ZDIM + gate * 512 + j0 + jjq * 4);
        int n = gate * 16 + jjq * 4;
        Bs[k][n + 0] = tf32cvt(v.x);
        Bs[k][n + 1] = tf32cvt(v.y);
        Bs[k][n + 2] = tf32cvt(v.z);
        Bs[k][n + 3] = tf32cvt(v.w);
    }
    __syncthreads();

    // cell state: thread's 4 items (item = tid + it*256 -> row item>>4, col item&15)
    float c_reg[4] = {0.0f, 0.0f, 0.0f, 0.0f};

    for (int t = 0; t < SEQ; t++) {
        // ---- wait for xz[t] (producer publishes 16 n-tiles per t) ----
        if (tid == 0) {
            while (atomicAdd(&g_ready[t], 0u) < 16u) { __nanosleep(64); }
        }
        __syncthreads();

        // ---- prefetch xz gate pre-activations into registers ----
        float xf[16];
        {
            const float* xz = g_xz + (size_t)t * BATCH * ZDIM;
            #pragma unroll
            for (int it = 0; it < 4; it++) {
                int item = tid + it * 256;
                int b = item >> 4, jj = item & 15;
                const float* p = xz + (size_t)(row0 + b) * ZDIM + j0 + jj;
                xf[it * 4 + 0] = p[0];
                xf[it * 4 + 1] = p[512];
                xf[it * 4 + 2] = p[1024];
                xf[it * 4 + 3] = p[1536];
            }
        }

        if (t > 0) {
            const float* hp = out + (size_t)(t - 1) * NBH;
            float acc[2][4][4];
            #pragma unroll
            for (int mt = 0; mt < 2; mt++)
                #pragma unroll
                for (int nt = 0; nt < 4; nt++)
                    #pragma unroll
                    for (int r = 0; r < 4; r++) acc[mt][nt][r] = 0.0f;

            #pragma unroll 1
            for (int p2 = 0; p2 < 2; p2++) {
                // load h rows [row0, row0+64) x k [p2*256, p2*256+256)
                // first 128 k -> As0 (group 0), next 128 k -> As1 (group 1)
                #pragma unroll
                for (int i = 0; i < 16; i++) {
                    int idx = tid + i * 256;          // 4096 float4s
                    int r = idx >> 6, c4 = idx & 63;
                    float4 v = *(const float4*)(hp + (size_t)(row0 + r) * HID + p2 * 256 + c4 * 4);
                    unsigned* dst = (c4 < 32) ? &As0[r][c4 * 4] : &As1[r][(c4 - 32) * 4];
                    *(uint4*)dst = make_uint4(tf32cvt(v.x), tf32cvt(v.y),
                                              tf32cvt(v.z), tf32cvt(v.w));
                }
                __syncthreads();

                unsigned (*A)[AS_STR] = grp ? As1 : As0;
                const int kb = p2 * 256 + grp * 128;   // B k-offset
                #pragma unroll
                for (int kk = 0; kk < 128; kk += 8) {
                    unsigned a[2][4], b[4][2];
                    #pragma unroll
                    for (int mt = 0; mt < 2; mt++) {
                        int mr = wm + mt * 16;
                        a[mt][0] = A[mr + gid][kk + tig];
                        a[mt][1] = A[mr + gid + 8][kk + tig];
                        a[mt][2] = A[mr + gid][kk + tig + 4];
                        a[mt][3] = A[mr + gid + 8][kk + tig + 4];
                    }
                    #pragma unroll
                    for (int nt = 0; nt < 4; nt++) {
                        int nc = wn + nt * 8;
                        b[nt][0] = Bs[kb + kk + tig][nc + gid];
                        b[nt][1] = Bs[kb + kk + tig + 4][nc + gid];
                    }
                    #pragma unroll
                    for (int mt = 0; mt < 2; mt++)
                        #pragma unroll
                        for (int nt = 0; nt < 4; nt++)
                            mma_tf32(acc[mt][nt], a[mt], b[nt]);
                }
                __syncthreads();
            }

            // ---- reduce the two K-groups through Zs ----
            if (grp == 0) {
                #pragma unroll
                for (int mt = 0; mt < 2; mt++)
                    #pragma unroll
                    for (int nt = 0; nt < 4; nt++) {
                        int rr  = wm + mt * 16 + gid;
                        int col = wn + nt * 8 + 2 * tig;
                        Zs[rr][col]         = acc[mt][nt][0];
                        Zs[rr][col + 1]     = acc[mt][nt][1];
                        Zs[rr + 8][col]     = acc[mt][nt][2];
                        Zs[rr + 8][col + 1] = acc[mt][nt][3];
                    }
            }
            __syncthreads();
            if (grp == 1) {
                #pragma unroll
                for (int mt = 0; mt < 2; mt++)
                    #pragma unroll
                    for (int nt = 0; nt < 4; nt++) {
                        int rr  = wm + mt * 16 + gid;
                        int col = wn + nt * 8 + 2 * tig;
                        Zs[rr][col]         += acc[mt][nt][0];
                        Zs[rr][col + 1]     += acc[mt][nt][1];
                        Zs[rr + 8][col]     += acc[mt][nt][2];
                        Zs[rr + 8][col + 1] += acc[mt][nt][3];
                    }
            }
            __syncthreads();
        }

        // ---- gates + state update: 4 items per thread ----
        float* hout = out + (size_t)t * NBH;
        #pragma unroll
        for (int it = 0; it < 4; it++) {
            int item = tid + it * 256;
            int b = item >> 4, jj = item & 15;
            float zr_i = (t > 0) ? Zs[b][jj]      : 0.0f;
            float zr_f = (t > 0) ? Zs[b][16 + jj] : 0.0f;
            float zr_g = (t > 0) ? Zs[b][32 + jj] : 0.0f;
            float zr_o = (t > 0) ? Zs[b][48 + jj] : 0.0f;
            float ig = sigm_ap(zr_i + xf[it * 4 + 0]);
            float fg = sigm_ap(zr_f + xf[it * 4 + 1]);
            float gg = tanh_ap(zr_g + xf[it * 4 + 2]);
            float og = sigm_ap(zr_o + xf[it * 4 + 3]);
            float cn = fg * c_reg[it] + ig * gg;
            c_reg[it] = cn;
            hout[(size_t)(row0 + b) * HID + j0 + jj] = og * tanh_ap(cn);
        }

        grid_sync((unsigned)(t + 1));
    }

    // ---- epilogue: append hT and cT ----
    {
        const float* hlast = out + (size_t)(SEQ - 1) * NBH;
        float* hT = out + (size_t)SEQ * NBH;
        float* cT = hT + NBH;
        #pragma unroll
        for (int it = 0; it < 4; it++) {
            int item = tid + it * 256;
            int b = item >> 4, jj = item & 15;
            size_t ci = (size_t)(row0 + b) * HID + j0 + jj;
            hT[ci] = hlast[ci];
            cT[ci] = c_reg[it];
        }
    }
}

// ---------------------------------------------------------------------------
extern "C" void kernel_launch(void* const* d_in, const int* in_sizes, int n_in,
                              void* d_out, int out_size) {
    const float* x    = (const float*)d_in[0];
    const float* W    = (const float*)d_in[1];
    const float* bias = (const float*)d_in[2];
    float* out = (float*)d_out;

    cudaFuncSetAttribute(lstm_persist_k,
                         cudaFuncAttributeMaxDynamicSharedMemorySize, SMEM_BYTES);

    reset_k<<<1, 1024>>>();
    lstm_persist_k<<<NREC + NPROD, 256, SMEM_BYTES>>>(out, x, W, bias);
}